// round 7
// baseline (speedup 1.0000x reference)
#include <cuda_runtime.h>
#include <cuda_fp16.h>
#include <cstdint>

#define GN 4096
#define DIN 64
#define DOUT 64
#define TOPK 4
#define SCALE_I 131072.0f                   // 2^17
#define SCALE_I2 17179869184.0f             // 2^34

// ---------------- scratch (static device globals; no allocs allowed) --------
__device__ int8_t g_Sb [GN*(size_t)GN];   // round(S * 2^17), row-major   (16MB)
__device__ int8_t g_SbT[GN*(size_t)GN];   // transpose of the same        (16MB)
__device__ float  g_S2 [GN*(size_t)GN];   // (S*2^17)@(S*2^17) as float   (64MB)
__device__ float  g_dinv[GN];
__device__ float  g_rS[GN];
__device__ float  g_rs2[GN];    // rowsum(S2)*2^34 (atomic-accumulated)
__device__ float  g_dinv2[GN];
__device__ float  g_t[2];
__device__ float  g_y[GN*DOUT];

// ---------------- small helpers --------------------------------------------
__device__ __forceinline__ float blk_reduce_sum(float s) {
    __shared__ float sm[8];
    for (int o = 16; o; o >>= 1) s += __shfl_down_sync(0xffffffffu, s, o);
    if ((threadIdx.x & 31) == 0) sm[threadIdx.x >> 5] = s;
    __syncthreads();
    float v = 0.f;
    if (threadIdx.x < 8) {
        v = sm[threadIdx.x];
        for (int o = 4; o; o >>= 1) v += __shfl_down_sync(0xffu, v, o);
    }
    return v;
}

__global__ void k_zero() {
    int i = blockIdx.x * blockDim.x + threadIdx.x;
    if (i < GN) g_rs2[i] = 0.f;
}

__global__ void k_rowsumA(const float* __restrict__ A) {
    int row = blockIdx.x;
    const float4* Ar = reinterpret_cast<const float4*>(A + (size_t)row * GN);
    float s = 0.f;
    for (int j = threadIdx.x; j < GN / 4; j += blockDim.x) {
        float4 v = Ar[j];
        s += v.x + v.y + v.z + v.w;
    }
    float tot = blk_reduce_sum(s);
    if (threadIdx.x == 0) g_dinv[row] = rsqrtf(tot);
}

__global__ void k_rowsumS(const float* __restrict__ A) {
    int row = blockIdx.x;
    const float4* Ar = reinterpret_cast<const float4*>(A + (size_t)row * GN);
    const float4* Dv = reinterpret_cast<const float4*>(g_dinv);
    float s = 0.f;
    for (int j = threadIdx.x; j < GN / 4; j += blockDim.x) {
        float4 a = Ar[j];
        float4 d = Dv[j];
        s += a.x * d.x + a.y * d.y + a.z * d.z + a.w * d.w;
    }
    float tot = blk_reduce_sum(s);
    if (threadIdx.x == 0) g_rS[row] = g_dinv[row] * tot;
}

// build Sb (int8, *2^17) and SbT (transpose), clean R2-style (no atomics)
__global__ void k_build(const float* __restrict__ A) {
    __shared__ float tile[32][33];
    int bx = blockIdx.x, by = blockIdx.y;
    int tx = threadIdx.x, ty = threadIdx.y;
    int col = bx * 32 + tx;
    float dc = g_dinv[col];
#pragma unroll
    for (int r = 0; r < 4; r++) {
        int row = by * 32 + ty + r * 8;
        float v = A[(size_t)row * GN + col] * g_dinv[row] * dc * SCALE_I;
        tile[ty + r * 8][tx] = v;
        int q = __float2int_rn(v);
        g_Sb[(size_t)row * GN + col] = (int8_t)max(-128, min(127, q));
    }
    __syncthreads();
#pragma unroll
    for (int r = 0; r < 4; r++) {
        int orow = bx * 32 + ty + r * 8;
        int ocol = by * 32 + tx;
        int q = __float2int_rn(tile[tx][ty + r * 8]);
        g_SbT[(size_t)orow * GN + ocol] = (int8_t)max(-128, min(127, q));
    }
}

// ---------------- IMMA int8 GEMM: S2 = Sb @ SbT^T ---------------------------
// CTA tile 256Mx128N, K-chunk 128 (int8 = 128B SW128 rows), 8 warps (64x64),
// 3-stage cp.async. Epilogue: float convert + fused rowsum(S2).
#define ST 3
#define KC 128
#define NC (GN / KC)                 // 32
#define A_BYTES (256 * 128)          // 32KB
#define B_BYTES (128 * 128)          // 16KB
#define STAGE_BYTES (A_BYTES + B_BYTES)
#define DYN_SMEM (ST * STAGE_BYTES)

__device__ __forceinline__ uint32_t sw128(uint32_t off) {
    return off ^ ((off >> 3) & 0x70);
}

__global__ void __launch_bounds__(256, 1) k_gemm() {
    extern __shared__ char dsm[];
    uint32_t sbase;
    asm("{ .reg .u64 t; cvta.to.shared.u64 t, %1; cvt.u32.u64 %0, t; }"
        : "=r"(sbase) : "l"(dsm));

    const int8_t* Ag = g_Sb;
    const int8_t* Bg = g_SbT;
    int tid = threadIdx.x, warp = tid >> 5, lane = tid & 31;
    int wm = warp & 3;
    int wn = warp >> 2;
    int rowBase = blockIdx.y * 256;
    int colBase = blockIdx.x * 128;

    int acc[4][8][4];
#pragma unroll
    for (int a = 0; a < 4; a++)
#pragma unroll
        for (int b = 0; b < 8; b++)
#pragma unroll
            for (int c = 0; c < 4; c++) acc[a][b][c] = 0;

    auto load_chunk = [&](int j) {
        uint32_t st0 = sbase + (j % ST) * STAGE_BYTES;
        int k0 = j * KC;
#pragma unroll
        for (int t = 0; t < 12; t++) {
            int q = tid + t * 256;            // 0..3071 16B ops
            const int8_t* src;
            uint32_t dst;
            if (q < 2048) {                   // A: 256 rows x 8 x 16B
                int r = q >> 3, c16 = q & 7;
                src = Ag + (size_t)(rowBase + r) * GN + k0 + c16 * 16;
                dst = st0 + sw128(r * 128 + c16 * 16);
            } else {                          // B: 128 rows x 8 x 16B
                int idx = q - 2048;
                int r = idx >> 3, c16 = idx & 7;
                src = Bg + (size_t)(colBase + r) * GN + k0 + c16 * 16;
                dst = st0 + A_BYTES + sw128(r * 128 + c16 * 16);
            }
            asm volatile("cp.async.cg.shared.global [%0],[%1],16;\n" :: "r"(dst), "l"(src));
        }
        asm volatile("cp.async.commit_group;\n");
    };

    load_chunk(0);
    load_chunk(1);

    for (int i = 0; i < NC; i++) {
        if (i + 2 < NC) load_chunk(i + 2);
        else asm volatile("cp.async.commit_group;\n");
        asm volatile("cp.async.wait_group 2;\n");
        __syncthreads();

        uint32_t aB = sbase + (i % ST) * STAGE_BYTES;
        uint32_t bB = aB + A_BYTES;
#pragma unroll
        for (int ks = 0; ks < 4; ks++) {
            int kb = ks * 32;                 // byte offset in 128B row
            uint32_t af[4][4];
#pragma unroll
            for (int mt = 0; mt < 4; mt++) {
                int m = wm * 64 + mt * 16 + (lane & 15);
                uint32_t off = m * 128 + kb + (lane >> 4) * 16;
                uint32_t addr = aB + sw128(off);
                asm volatile("ldmatrix.sync.aligned.m8n8.x4.shared.b16 {%0,%1,%2,%3},[%4];"
                             : "=r"(af[mt][0]), "=r"(af[mt][1]), "=r"(af[mt][2]), "=r"(af[mt][3])
                             : "r"(addr));
            }
            uint32_t bf[8][2];
#pragma unroll
            for (int nb = 0; nb < 4; nb++) {
                int sel = lane >> 3;
                int nn = wn * 64 + nb * 16 + (sel >> 1) * 8 + (lane & 7);
                uint32_t off = nn * 128 + kb + (sel & 1) * 16;
                uint32_t addr = bB + sw128(off);
                uint32_t r0, r1, r2, r3;
                asm volatile("ldmatrix.sync.aligned.m8n8.x4.shared.b16 {%0,%1,%2,%3},[%4];"
                             : "=r"(r0), "=r"(r1), "=r"(r2), "=r"(r3) : "r"(addr));
                bf[nb * 2][0] = r0; bf[nb * 2][1] = r1;
                bf[nb * 2 + 1][0] = r2; bf[nb * 2 + 1][1] = r3;
            }
#pragma unroll
            for (int mt = 0; mt < 4; mt++)
#pragma unroll
                for (int nt = 0; nt < 8; nt++) {
                    asm volatile(
                        "mma.sync.aligned.m16n8k32.row.col.s32.s8.s8.s32 "
                        "{%0,%1,%2,%3},{%4,%5,%6,%7},{%8,%9},{%0,%1,%2,%3};"
                        : "+r"(acc[mt][nt][0]), "+r"(acc[mt][nt][1]),
                          "+r"(acc[mt][nt][2]), "+r"(acc[mt][nt][3])
                        : "r"(af[mt][0]), "r"(af[mt][1]), "r"(af[mt][2]), "r"(af[mt][3]),
                          "r"(bf[nt][0]), "r"(bf[nt][1]));
                }
        }
        __syncthreads();
    }

    // epilogue: s32 -> float store + fused rowsum(S2)
#pragma unroll
    for (int mt = 0; mt < 4; mt++) {
        float rsA = 0.f, rsB = 0.f;
#pragma unroll
        for (int nt = 0; nt < 8; nt++) {
            int m0 = rowBase + wm * 64 + mt * 16 + (lane >> 2);
            int n0 = colBase + wn * 64 + nt * 8 + (lane & 3) * 2;
            float c0 = __int2float_rn(acc[mt][nt][0]);
            float c1 = __int2float_rn(acc[mt][nt][1]);
            float c2 = __int2float_rn(acc[mt][nt][2]);
            float c3 = __int2float_rn(acc[mt][nt][3]);
            *reinterpret_cast<float2*>(g_S2 + (size_t)m0 * GN + n0) = make_float2(c0, c1);
            *reinterpret_cast<float2*>(g_S2 + (size_t)(m0 + 8) * GN + n0) = make_float2(c2, c3);
            rsA += c0 + c1;
            rsB += c2 + c3;
        }
        rsA += __shfl_xor_sync(0xffffffffu, rsA, 1);
        rsA += __shfl_xor_sync(0xffffffffu, rsA, 2);
        rsB += __shfl_xor_sync(0xffffffffu, rsB, 1);
        rsB += __shfl_xor_sync(0xffffffffu, rsB, 2);
        if ((lane & 3) == 0) {
            int m0 = rowBase + wm * 64 + mt * 16 + (lane >> 2);
            atomicAdd(&g_rs2[m0], rsA);
            atomicAdd(&g_rs2[m0 + 8], rsB);
        }
    }
}

__global__ void k_sig(const float* __restrict__ theta) {
    if (threadIdx.x < 2) g_t[threadIdx.x] = 1.0f / (1.0f + expf(-theta[threadIdx.x]));
}

__global__ void k_d2() {
    int i = blockIdx.x * blockDim.x + threadIdx.x;
    if (i < GN) {
        float d2 = 1.0f + g_t[0] * g_rS[i] + g_t[1] * (g_rs2[i] * (1.0f / SCALE_I2));
        g_dinv2[i] = rsqrtf(d2);
    }
}

// y = x @ W^T
__global__ void k_xw(const float* __restrict__ x, const float* __restrict__ W) {
    __shared__ float Wt[DIN * DOUT];
    __shared__ float xr[DIN];
    int row = blockIdx.x;
    for (int i = threadIdx.x; i < DOUT * DIN; i += 64) {
        int c = i / DIN, d = i % DIN;
        Wt[d * DOUT + c] = W[i];
    }
    if (threadIdx.x < DIN) xr[threadIdx.x] = x[row * DIN + threadIdx.x];
    __syncthreads();
    int c = threadIdx.x;
    float s = 0.f;
#pragma unroll
    for (int d = 0; d < DIN; d++) s += xr[d] * Wt[d * DOUT + c];
    g_y[row * DOUT + c] = s;
}

// ---------------- top-4 per row + sparse output -----------------------------
__device__ __forceinline__ void topk_insert(float c, int j, float* v, int* id) {
    if (c > v[3] || (c == v[3] && j < id[3])) {
        v[3] = c; id[3] = j;
#pragma unroll
        for (int s = 3; s > 0; s--) {
            if (v[s] > v[s - 1] || (v[s] == v[s - 1] && id[s] < id[s - 1])) {
                float tv = v[s]; v[s] = v[s - 1]; v[s - 1] = tv;
                int ti = id[s]; id[s] = id[s - 1]; id[s - 1] = ti;
            }
        }
    }
}

__global__ void k_topk(const float* __restrict__ A, const float* __restrict__ b,
                       float* __restrict__ out) {
    int i   = blockIdx.x;
    int tid = threadIdx.x;
    float t0  = g_t[0];
    float t1s = g_t[1] * (1.0f / SCALE_I2);
    float di  = g_dinv[i];
    const float* Ar = A    + (size_t)i * GN;
    const float* Sr = g_S2 + (size_t)i * GN;

    float vb[4] = {-1e30f, -1e30f, -1e30f, -1e30f};
    int   ib[4] = {0x7fffffff, 0x7fffffff, 0x7fffffff, 0x7fffffff};

    for (int j = tid; j < GN; j += 128) {
        float p = t0 * (Ar[j] * di * g_dinv[j]) + t1s * Sr[j];
        if (j == i) p += 1.0f;
        float c = p * g_dinv2[j];
        topk_insert(c, j, vb, ib);
    }

    __shared__ float sv[128 * 4];
    __shared__ int   si[128 * 4];
#pragma unroll
    for (int s = 0; s < 4; s++) { sv[tid * 4 + s] = vb[s]; si[tid * 4 + s] = ib[s]; }
    __syncthreads();

    __shared__ float fv[4];
    __shared__ int   fi[4];
    if (tid == 0) {
        float bv[4] = {-1e30f, -1e30f, -1e30f, -1e30f};
        int   bi[4] = {0x7fffffff, 0x7fffffff, 0x7fffffff, 0x7fffffff};
        for (int q = 0; q < 128 * 4; q++) topk_insert(sv[q], si[q], bv, bi);
#pragma unroll
        for (int s = 0; s < 4; s++) { fv[s] = bv[s]; fi[s] = bi[s]; }
    }
    __syncthreads();

    if (tid < DOUT) {
        float di2 = g_dinv2[i];
        float s = b[tid];
#pragma unroll
        for (int q = 0; q < TOPK; q++)
            s += di2 * fv[q] * g_y[fi[q] * DOUT + tid];
        out[(size_t)i * DOUT + tid] = s;
    }
}

// ---------------- launch -----------------------------------------------------
extern "C" void kernel_launch(void* const* d_in, const int* in_sizes, int n_in,
                              void* d_out, int out_size) {
    const float* x     = (const float*)d_in[0];
    const float* A     = (const float*)d_in[1];
    const float* theta = (const float*)d_in[2];
    const float* W     = (const float*)d_in[3];
    const float* b     = (const float*)d_in[4];
    float* out = (float*)d_out;

    cudaFuncSetAttribute(k_gemm, cudaFuncAttributeMaxDynamicSharedMemorySize, DYN_SMEM);

    k_zero<<<(GN + 255) / 256, 256>>>();
    k_rowsumA<<<GN, 256>>>(A);
    k_sig<<<1, 32>>>(theta);
    k_rowsumS<<<GN, 256>>>(A);
    k_build<<<dim3(128, 128), dim3(32, 8)>>>(A);
    k_gemm<<<dim3(GN / 128, GN / 256), 256, DYN_SMEM>>>();
    k_d2<<<16, 256>>>();
    k_xw<<<GN, 64>>>(x, W);
    k_topk<<<GN, 128>>>(A, b, out);
}

// round 12
// speedup vs baseline: 2.4169x; 2.4169x over previous
#include <cuda_runtime.h>
#include <cuda_fp16.h>
#include <cstdint>

#define GN 4096
#define DIN 64
#define DOUT 64
#define TOPK 4
#define SCALE 2048.0f
#define SCALE2 (2048.0f*2048.0f)

// ---------------- scratch (static device globals; no allocs allowed) --------
__device__ __half g_Sh [GN*(size_t)GN];   // S*SCALE, row-major  [i][k]  (32MB)
__device__ __half g_ShT[GN*(size_t)GN];   // S^T*SCALE                   (32MB)
__device__ float  g_S2 [GN*(size_t)GN];   // (S*SCALE)@(S*SCALE)          (64MB)
__device__ float  g_dinv[GN];
__device__ float  g_rS[GN];
__device__ float  g_rs2[GN];    // rowsum(S2)*SCALE2 (atomic-accumulated)
__device__ float  g_dinv2[GN];
__device__ float  g_t[2];
__device__ float  g_y[GN*DOUT];

// ---------------- small helpers --------------------------------------------
__device__ __forceinline__ float blk_reduce_sum(float s) {
    __shared__ float sm[8];
    for (int o = 16; o; o >>= 1) s += __shfl_down_sync(0xffffffffu, s, o);
    if ((threadIdx.x & 31) == 0) sm[threadIdx.x >> 5] = s;
    __syncthreads();
    float v = 0.f;
    if (threadIdx.x < 8) {
        v = sm[threadIdx.x];
        for (int o = 4; o; o >>= 1) v += __shfl_down_sync(0xffu, v, o);
    }
    return v;
}

__global__ void k_zero() {
    int i = blockIdx.x * blockDim.x + threadIdx.x;
    if (i < GN) g_rs2[i] = 0.f;
}

__global__ void k_rowsumA(const float* __restrict__ A) {
    int row = blockIdx.x;
    const float4* Ar = reinterpret_cast<const float4*>(A + (size_t)row * GN);
    float s = 0.f;
    for (int j = threadIdx.x; j < GN / 4; j += blockDim.x) {
        float4 v = Ar[j];
        s += v.x + v.y + v.z + v.w;
    }
    float tot = blk_reduce_sum(s);
    if (threadIdx.x == 0) g_dinv[row] = rsqrtf(tot);
}

__global__ void k_rowsumS(const float* __restrict__ A) {
    int row = blockIdx.x;
    const float4* Ar = reinterpret_cast<const float4*>(A + (size_t)row * GN);
    const float4* Dv = reinterpret_cast<const float4*>(g_dinv);
    float s = 0.f;
    for (int j = threadIdx.x; j < GN / 4; j += blockDim.x) {
        float4 a = Ar[j];
        float4 d = Dv[j];
        s += a.x * d.x + a.y * d.y + a.z * d.z + a.w * d.w;
    }
    float tot = blk_reduce_sum(s);
    if (threadIdx.x == 0) g_rS[row] = g_dinv[row] * tot;
}

// build Sh + ShT (fp16, *SCALE), clean (no atomics)
__global__ void k_build(const float* __restrict__ A) {
    __shared__ float tile[32][33];
    int bx = blockIdx.x, by = blockIdx.y;
    int tx = threadIdx.x, ty = threadIdx.y;
    int col = bx * 32 + tx;
    float dc = g_dinv[col];
#pragma unroll
    for (int r = 0; r < 4; r++) {
        int row = by * 32 + ty + r * 8;
        float v = A[(size_t)row * GN + col] * g_dinv[row] * dc * SCALE;
        tile[ty + r * 8][tx] = v;
        g_Sh[(size_t)row * GN + col] = __float2half_rn(v);
    }
    __syncthreads();
#pragma unroll
    for (int r = 0; r < 4; r++) {
        int orow = bx * 32 + ty + r * 8;
        int ocol = by * 32 + tx;
        g_ShT[(size_t)orow * GN + ocol] = __float2half_rn(tile[tx][ty + r * 8]);
    }
}

// ---------------- HMMA GEMM: S2 = Sh @ ShT^T --------------------------------
// CTA tile 128x128, K-chunk 64 (128B SW128 rows), 8 warps (32x64 warp tile),
// 3-stage cp.async, 2 CTAs/SM. Epilogue fuses rowsum(S2).
#define ST 3
#define KC 64
#define NC (GN / KC)                 // 64
#define A_BYTES (128 * 128)          // 16KB
#define B_BYTES (128 * 128)          // 16KB
#define STAGE_BYTES (A_BYTES + B_BYTES)
#define DYN_SMEM (ST * STAGE_BYTES)  // 96KB

__device__ __forceinline__ uint32_t sw128(uint32_t off) {
    return off ^ ((off >> 3) & 0x70);
}

__global__ void __launch_bounds__(256, 2) k_gemm() {
    extern __shared__ char dsm[];
    uint32_t sbase;
    asm("{ .reg .u64 t; cvta.to.shared.u64 t, %1; cvt.u32.u64 %0, t; }"
        : "=r"(sbase) : "l"(dsm));

    const __half* Ag = g_Sh;
    const __half* Bg = g_ShT;
    int tid = threadIdx.x, warp = tid >> 5, lane = tid & 31;
    int wm = warp & 3;   // 4 slabs of 32 rows
    int wn = warp >> 2;  // 2 slabs of 64 cols
    int rowBase = blockIdx.y * 128;
    int colBase = blockIdx.x * 128;

    float acc[2][8][4];
#pragma unroll
    for (int a = 0; a < 2; a++)
#pragma unroll
        for (int b = 0; b < 8; b++)
#pragma unroll
            for (int c = 0; c < 4; c++) acc[a][b][c] = 0.f;

    auto load_chunk = [&](int j) {
        uint32_t st0 = sbase + (j % ST) * STAGE_BYTES;
        int k0 = j * KC;
#pragma unroll
        for (int t = 0; t < 8; t++) {
            int q = tid + t * 256;            // 0..2047 16B ops
            const __half* src;
            uint32_t dst;
            if (q < 1024) {                   // A: 128 rows x 8 x 16B
                int r = q >> 3, c16 = q & 7;
                src = Ag + (size_t)(rowBase + r) * GN + k0 + c16 * 8;
                dst = st0 + sw128(r * 128 + c16 * 16);
            } else {                          // B
                int idx = q - 1024;
                int r = idx >> 3, c16 = idx & 7;
                src = Bg + (size_t)(colBase + r) * GN + k0 + c16 * 8;
                dst = st0 + A_BYTES + sw128(r * 128 + c16 * 16);
            }
            asm volatile("cp.async.cg.shared.global [%0],[%1],16;\n" :: "r"(dst), "l"(src));
        }
        asm volatile("cp.async.commit_group;\n");
    };

    load_chunk(0);
    load_chunk(1);

    for (int i = 0; i < NC; i++) {
        if (i + 2 < NC) load_chunk(i + 2);
        else asm volatile("cp.async.commit_group;\n");
        asm volatile("cp.async.wait_group 2;\n");
        __syncthreads();

        uint32_t aB = sbase + (i % ST) * STAGE_BYTES;
        uint32_t bB = aB + A_BYTES;
#pragma unroll
        for (int ks = 0; ks < 4; ks++) {
            int kk = ks * 16;                 // k-halves within 64
            uint32_t af[2][4];
#pragma unroll
            for (int mt = 0; mt < 2; mt++) {
                int m = wm * 32 + mt * 16 + (lane & 15);
                uint32_t off = m * 128 + kk * 2 + (lane >> 4) * 16;
                uint32_t addr = aB + sw128(off);
                asm volatile("ldmatrix.sync.aligned.m8n8.x4.shared.b16 {%0,%1,%2,%3},[%4];"
                             : "=r"(af[mt][0]), "=r"(af[mt][1]), "=r"(af[mt][2]), "=r"(af[mt][3])
                             : "r"(addr));
            }
            uint32_t bf[8][2];
#pragma unroll
            for (int nb = 0; nb < 4; nb++) {
                int sel = lane >> 3;
                int nn = wn * 64 + nb * 16 + (sel >> 1) * 8 + (lane & 7);
                uint32_t off = nn * 128 + kk * 2 + (sel & 1) * 16;
                uint32_t addr = bB + sw128(off);
                uint32_t r0, r1, r2, r3;
                asm volatile("ldmatrix.sync.aligned.m8n8.x4.shared.b16 {%0,%1,%2,%3},[%4];"
                             : "=r"(r0), "=r"(r1), "=r"(r2), "=r"(r3) : "r"(addr));
                bf[nb * 2][0] = r0; bf[nb * 2][1] = r1;
                bf[nb * 2 + 1][0] = r2; bf[nb * 2 + 1][1] = r3;
            }
#pragma unroll
            for (int mt = 0; mt < 2; mt++)
#pragma unroll
                for (int nt = 0; nt < 8; nt++) {
                    asm volatile(
                        "mma.sync.aligned.m16n8k16.row.col.f32.f16.f16.f32 "
                        "{%0,%1,%2,%3},{%4,%5,%6,%7},{%8,%9},{%0,%1,%2,%3};"
                        : "+f"(acc[mt][nt][0]), "+f"(acc[mt][nt][1]),
                          "+f"(acc[mt][nt][2]), "+f"(acc[mt][nt][3])
                        : "r"(af[mt][0]), "r"(af[mt][1]), "r"(af[mt][2]), "r"(af[mt][3]),
                          "r"(bf[nt][0]), "r"(bf[nt][1]));
                }
        }
        __syncthreads();
    }

    // epilogue: store + fused rowsum(S2)
#pragma unroll
    for (int mt = 0; mt < 2; mt++) {
        float rsA = 0.f, rsB = 0.f;
#pragma unroll
        for (int nt = 0; nt < 8; nt++) {
            int m0 = rowBase + wm * 32 + mt * 16 + (lane >> 2);
            int n0 = colBase + wn * 64 + nt * 8 + (lane & 3) * 2;
            *reinterpret_cast<float2*>(g_S2 + (size_t)m0 * GN + n0) =
                make_float2(acc[mt][nt][0], acc[mt][nt][1]);
            *reinterpret_cast<float2*>(g_S2 + (size_t)(m0 + 8) * GN + n0) =
                make_float2(acc[mt][nt][2], acc[mt][nt][3]);
            rsA += acc[mt][nt][0] + acc[mt][nt][1];
            rsB += acc[mt][nt][2] + acc[mt][nt][3];
        }
        rsA += __shfl_xor_sync(0xffffffffu, rsA, 1);
        rsA += __shfl_xor_sync(0xffffffffu, rsA, 2);
        rsB += __shfl_xor_sync(0xffffffffu, rsB, 1);
        rsB += __shfl_xor_sync(0xffffffffu, rsB, 2);
        if ((lane & 3) == 0) {
            int m0 = rowBase + wm * 32 + mt * 16 + (lane >> 2);
            atomicAdd(&g_rs2[m0], rsA);
            atomicAdd(&g_rs2[m0 + 8], rsB);
        }
    }
}

__global__ void k_sig(const float* __restrict__ theta) {
    if (threadIdx.x < 2) g_t[threadIdx.x] = 1.0f / (1.0f + expf(-theta[threadIdx.x]));
}

__global__ void k_d2() {
    int i = blockIdx.x * blockDim.x + threadIdx.x;
    if (i < GN) {
        float d2 = 1.0f + g_t[0] * g_rS[i] + g_t[1] * (g_rs2[i] * (1.0f / SCALE2));
        g_dinv2[i] = rsqrtf(d2);
    }
}

// y = x @ W^T
__global__ void k_xw(const float* __restrict__ x, const float* __restrict__ W) {
    __shared__ float Wt[DIN * DOUT];
    __shared__ float xr[DIN];
    int row = blockIdx.x;
    for (int i = threadIdx.x; i < DOUT * DIN; i += 64) {
        int c = i / DIN, d = i % DIN;
        Wt[d * DOUT + c] = W[i];
    }
    if (threadIdx.x < DIN) xr[threadIdx.x] = x[row * DIN + threadIdx.x];
    __syncthreads();
    int c = threadIdx.x;
    float s = 0.f;
#pragma unroll
    for (int d = 0; d < DIN; d++) s += xr[d] * Wt[d * DOUT + c];
    g_y[row * DOUT + c] = s;
}

// ---------------- top-4 per row + sparse output -----------------------------
__device__ __forceinline__ void topk_insert(float c, int j, float* v, int* id) {
    if (c > v[3] || (c == v[3] && j < id[3])) {
        v[3] = c; id[3] = j;
#pragma unroll
        for (int s = 3; s > 0; s--) {
            if (v[s] > v[s - 1] || (v[s] == v[s - 1] && id[s] < id[s - 1])) {
                float tv = v[s]; v[s] = v[s - 1]; v[s - 1] = tv;
                int ti = id[s]; id[s] = id[s - 1]; id[s - 1] = ti;
            }
        }
    }
}

__global__ void k_topk(const float* __restrict__ A, const float* __restrict__ b,
                       float* __restrict__ out) {
    int i   = blockIdx.x;
    int tid = threadIdx.x;
    float t0  = g_t[0];
    float t1s = g_t[1] * (1.0f / SCALE2);
    float di  = g_dinv[i];
    const float* Ar = A    + (size_t)i * GN;
    const float* Sr = g_S2 + (size_t)i * GN;

    float vb[4] = {-1e30f, -1e30f, -1e30f, -1e30f};
    int   ib[4] = {0x7fffffff, 0x7fffffff, 0x7fffffff, 0x7fffffff};

    for (int j = tid; j < GN; j += 128) {
        float p = t0 * (Ar[j] * di * g_dinv[j]) + t1s * Sr[j];
        if (j == i) p += 1.0f;
        float c = p * g_dinv2[j];
        topk_insert(c, j, vb, ib);
    }

    __shared__ float sv[128 * 4];
    __shared__ int   si[128 * 4];
#pragma unroll
    for (int s = 0; s < 4; s++) { sv[tid * 4 + s] = vb[s]; si[tid * 4 + s] = ib[s]; }
    __syncthreads();

    __shared__ float fv[4];
    __shared__ int   fi[4];
    if (tid == 0) {
        float bv[4] = {-1e30f, -1e30f, -1e30f, -1e30f};
        int   bi[4] = {0x7fffffff, 0x7fffffff, 0x7fffffff, 0x7fffffff};
        for (int q = 0; q < 128 * 4; q++) topk_insert(sv[q], si[q], bv, bi);
#pragma unroll
        for (int s = 0; s < 4; s++) { fv[s] = bv[s]; fi[s] = bi[s]; }
    }
    __syncthreads();

    if (tid < DOUT) {
        float di2 = g_dinv2[i];
        float s = b[tid];
#pragma unroll
        for (int q = 0; q < TOPK; q++)
            s += di2 * fv[q] * g_y[fi[q] * DOUT + tid];
        out[(size_t)i * DOUT + tid] = s;
    }
}

// ---------------- launch -----------------------------------------------------
extern "C" void kernel_launch(void* const* d_in, const int* in_sizes, int n_in,
                              void* d_out, int out_size) {
    const float* x     = (const float*)d_in[0];
    const float* A     = (const float*)d_in[1];
    const float* theta = (const float*)d_in[2];
    const float* W     = (const float*)d_in[3];
    const float* b     = (const float*)d_in[4];
    float* out = (float*)d_out;

    cudaFuncSetAttribute(k_gemm, cudaFuncAttributeMaxDynamicSharedMemorySize, DYN_SMEM);

    k_zero<<<(GN + 255) / 256, 256>>>();
    k_rowsumA<<<GN, 256>>>(A);
    k_sig<<<1, 32>>>(theta);
    k_rowsumS<<<GN, 256>>>(A);
    k_build<<<dim3(128, 128), dim3(32, 8)>>>(A);
    k_gemm<<<dim3(GN / 128, GN / 128), 256, DYN_SMEM>>>();
    k_d2<<<16, 256>>>();
    k_xw<<<GN, 64>>>(x, W);
    k_topk<<<GN, 128>>>(A, b, out);
}

// round 15
// speedup vs baseline: 2.5229x; 1.0438x over previous
#include <cuda_runtime.h>
#include <cuda_fp16.h>
#include <cstdint>

#define GN 4096
#define DIN 64
#define DOUT 64
#define TOPK 4
#define SCALE 2048.0f
#define SCALE2 (2048.0f*2048.0f)

// ---------------- scratch (static device globals; no allocs allowed) --------
__device__ __half g_Sh [GN*(size_t)GN];   // S*SCALE, row-major  (32MB)
__device__ __half g_ShT[GN*(size_t)GN];   // S^T*SCALE           (32MB)
__device__ float  g_dinv[GN];
__device__ float  g_rS[GN];               // rowsum(S)
__device__ float  g_dinv2[GN];
__device__ float  g_t[2];
__device__ float  g_y[GN*DOUT];
__device__ float  g_cv[GN*(size_t)128];   // per-(row, colblock) top-4 values (2MB)
__device__ int    g_ci[GN*(size_t)128];   // and indices                      (2MB)

// ---------------- small helpers --------------------------------------------
__device__ __forceinline__ float blk_reduce_sum(float s) {
    __shared__ float sm[8];
    for (int o = 16; o; o >>= 1) s += __shfl_down_sync(0xffffffffu, s, o);
    if ((threadIdx.x & 31) == 0) sm[threadIdx.x >> 5] = s;
    __syncthreads();
    float v = 0.f;
    if (threadIdx.x < 8) {
        v = sm[threadIdx.x];
        for (int o = 4; o; o >>= 1) v += __shfl_down_sync(0xffu, v, o);
    }
    return v;
}

__global__ void k_rowsumA(const float* __restrict__ A) {
    int row = blockIdx.x;
    const float4* Ar = reinterpret_cast<const float4*>(A + (size_t)row * GN);
    float s = 0.f;
    for (int j = threadIdx.x; j < GN / 4; j += blockDim.x) {
        float4 v = Ar[j];
        s += v.x + v.y + v.z + v.w;
    }
    float tot = blk_reduce_sum(s);
    if (threadIdx.x == 0) g_dinv[row] = rsqrtf(tot);
}

__global__ void k_sig(const float* __restrict__ theta) {
    if (threadIdx.x < 2) g_t[threadIdx.x] = 1.0f / (1.0f + expf(-theta[threadIdx.x]));
}

// build Sh + ShT (fp16, *SCALE)
__global__ void k_build(const float* __restrict__ A) {
    __shared__ float tile[32][33];
    int bx = blockIdx.x, by = blockIdx.y;
    int tx = threadIdx.x, ty = threadIdx.y;
    int col = bx * 32 + tx;
    float dc = g_dinv[col];
#pragma unroll
    for (int r = 0; r < 4; r++) {
        int row = by * 32 + ty + r * 8;
        float v = A[(size_t)row * GN + col] * g_dinv[row] * dc * SCALE;
        tile[ty + r * 8][tx] = v;
        g_Sh[(size_t)row * GN + col] = __float2half_rn(v);
    }
    __syncthreads();
#pragma unroll
    for (int r = 0; r < 4; r++) {
        int orow = bx * 32 + ty + r * 8;
        int ocol = by * 32 + tx;
        g_ShT[(size_t)orow * GN + ocol] = __float2half_rn(tile[tx][ty + r * 8]);
    }
}

// rS[i] = rowsum(S)[i] = (1/SCALE) * sum_j Sh[i,j]
__global__ void k_rS() {
    int row = blockIdx.x;
    const uint4* Sr = reinterpret_cast<const uint4*>(g_Sh + (size_t)row * GN);
    float s = 0.f;
    for (int q = threadIdx.x; q < GN / 8; q += blockDim.x) {
        uint4 u = Sr[q];
        const __half2* h = reinterpret_cast<const __half2*>(&u);
#pragma unroll
        for (int e = 0; e < 4; e++) {
            float2 f = __half22float2(h[e]);
            s += f.x + f.y;
        }
    }
    float tot = blk_reduce_sum(s);
    if (threadIdx.x == 0) g_rS[row] = tot * (1.0f / SCALE);
}

// rs2[i] = (S @ rS)[i]; then dinv2[i] = rsqrt(1 + t0*rS + t1*rs2)
__global__ void k_rs2d2() {
    int row = blockIdx.x;
    const uint4* Sr = reinterpret_cast<const uint4*>(g_Sh + (size_t)row * GN);
    float s = 0.f;
    for (int q = threadIdx.x; q < GN / 8; q += blockDim.x) {
        uint4 u = Sr[q];
        const __half2* h = reinterpret_cast<const __half2*>(&u);
        const float* rv = g_rS + q * 8;
#pragma unroll
        for (int e = 0; e < 4; e++) {
            float2 f = __half22float2(h[e]);
            s += f.x * rv[2 * e] + f.y * rv[2 * e + 1];
        }
    }
    float tot = blk_reduce_sum(s);
    if (threadIdx.x == 0) {
        float rs2 = tot * (1.0f / SCALE);
        float d2 = 1.0f + g_t[0] * g_rS[row] + g_t[1] * rs2;
        g_dinv2[row] = rsqrtf(d2);
    }
}

// y = x @ W^T
__global__ void k_xw(const float* __restrict__ x, const float* __restrict__ W) {
    __shared__ float Wt[DIN * DOUT];
    __shared__ float xr[DIN];
    int row = blockIdx.x;
    for (int i = threadIdx.x; i < DOUT * DIN; i += 64) {
        int c = i / DIN, d = i % DIN;
        Wt[d * DOUT + c] = W[i];
    }
    if (threadIdx.x < DIN) xr[threadIdx.x] = x[row * DIN + threadIdx.x];
    __syncthreads();
    int c = threadIdx.x;
    float s = 0.f;
#pragma unroll
    for (int d = 0; d < DIN; d++) s += xr[d] * Wt[d * DOUT + c];
    g_y[row * DOUT + c] = s;
}

// ---------------- top-k primitive ------------------------------------------
__device__ __forceinline__ void topk_insert(float c, int j, float* v, int* id) {
    if (c > v[3] || (c == v[3] && j < id[3])) {
        v[3] = c; id[3] = j;
#pragma unroll
        for (int s = 3; s > 0; s--) {
            if (v[s] > v[s - 1] || (v[s] == v[s - 1] && id[s] < id[s - 1])) {
                float tv = v[s]; v[s] = v[s - 1]; v[s - 1] = tv;
                int ti = id[s]; id[s] = id[s - 1]; id[s - 1] = ti;
            }
        }
    }
}

// ---------------- HMMA GEMM + fused top-4 candidate epilogue ---------------
// CTA tile 128x128, K-chunk 64 (128B SW128 rows), 8 warps (32x64), 3-stage
// cp.async, 2 CTAs/SM. Epilogue computes c = (t0*S + t1*S2/SC2 + diag)*dinv2[j]
// exactly (S recomputed from A) and emits per-row top-4 over this 128-col block.
#define ST 3
#define KC 64
#define NC (GN / KC)
#define A_BYTES (128 * 128)
#define B_BYTES (128 * 128)
#define STAGE_BYTES (A_BYTES + B_BYTES)
#define DYN_SMEM (ST * STAGE_BYTES)  // 96KB

__device__ __forceinline__ uint32_t sw128(uint32_t off) {
    return off ^ ((off >> 3) & 0x70);
}

__global__ void __launch_bounds__(256, 2) k_gemm(const float* __restrict__ A) {
    extern __shared__ char dsm[];
    uint32_t sbase;
    asm("{ .reg .u64 t; cvta.to.shared.u64 t, %1; cvt.u32.u64 %0, t; }"
        : "=r"(sbase) : "l"(dsm));

    const __half* Ag = g_Sh;
    const __half* Bg = g_ShT;
    int tid = threadIdx.x, warp = tid >> 5, lane = tid & 31;
    int wm = warp & 3;
    int wn = warp >> 2;
    int rowBase = blockIdx.y * 128;
    int colBase = blockIdx.x * 128;

    float acc[2][8][4];
#pragma unroll
    for (int a = 0; a < 2; a++)
#pragma unroll
        for (int b = 0; b < 8; b++)
#pragma unroll
            for (int c = 0; c < 4; c++) acc[a][b][c] = 0.f;

    auto load_chunk = [&](int j) {
        uint32_t st0 = sbase + (j % ST) * STAGE_BYTES;
        int k0 = j * KC;
#pragma unroll
        for (int t = 0; t < 8; t++) {
            int q = tid + t * 256;
            const __half* src;
            uint32_t dst;
            if (q < 1024) {
                int r = q >> 3, c16 = q & 7;
                src = Ag + (size_t)(rowBase + r) * GN + k0 + c16 * 8;
                dst = st0 + sw128(r * 128 + c16 * 16);
            } else {
                int idx = q - 1024;
                int r = idx >> 3, c16 = idx & 7;
                src = Bg + (size_t)(colBase + r) * GN + k0 + c16 * 8;
                dst = st0 + A_BYTES + sw128(r * 128 + c16 * 16);
            }
            asm volatile("cp.async.cg.shared.global [%0],[%1],16;\n" :: "r"(dst), "l"(src));
        }
        asm volatile("cp.async.commit_group;\n");
    };

    load_chunk(0);
    load_chunk(1);

    for (int i = 0; i < NC; i++) {
        if (i + 2 < NC) load_chunk(i + 2);
        else asm volatile("cp.async.commit_group;\n");
        asm volatile("cp.async.wait_group 2;\n");
        __syncthreads();

        uint32_t aB = sbase + (i % ST) * STAGE_BYTES;
        uint32_t bB = aB + A_BYTES;
#pragma unroll
        for (int ks = 0; ks < 4; ks++) {
            int kk = ks * 16;
            uint32_t af[2][4];
#pragma unroll
            for (int mt = 0; mt < 2; mt++) {
                int m = wm * 32 + mt * 16 + (lane & 15);
                uint32_t off = m * 128 + kk * 2 + (lane >> 4) * 16;
                uint32_t addr = aB + sw128(off);
                asm volatile("ldmatrix.sync.aligned.m8n8.x4.shared.b16 {%0,%1,%2,%3},[%4];"
                             : "=r"(af[mt][0]), "=r"(af[mt][1]), "=r"(af[mt][2]), "=r"(af[mt][3])
                             : "r"(addr));
            }
            uint32_t bf[8][2];
#pragma unroll
            for (int nb = 0; nb < 4; nb++) {
                int sel = lane >> 3;
                int nn = wn * 64 + nb * 16 + (sel >> 1) * 8 + (lane & 7);
                uint32_t off = nn * 128 + kk * 2 + (sel & 1) * 16;
                uint32_t addr = bB + sw128(off);
                uint32_t r0, r1, r2, r3;
                asm volatile("ldmatrix.sync.aligned.m8n8.x4.shared.b16 {%0,%1,%2,%3},[%4];"
                             : "=r"(r0), "=r"(r1), "=r"(r2), "=r"(r3) : "r"(addr));
                bf[nb * 2][0] = r0; bf[nb * 2][1] = r1;
                bf[nb * 2 + 1][0] = r2; bf[nb * 2 + 1][1] = r3;
            }
#pragma unroll
            for (int mt = 0; mt < 2; mt++)
#pragma unroll
                for (int nt = 0; nt < 8; nt++) {
                    asm volatile(
                        "mma.sync.aligned.m16n8k16.row.col.f32.f16.f16.f32 "
                        "{%0,%1,%2,%3},{%4,%5,%6,%7},{%8,%9},{%0,%1,%2,%3};"
                        : "+f"(acc[mt][nt][0]), "+f"(acc[mt][nt][1]),
                          "+f"(acc[mt][nt][2]), "+f"(acc[mt][nt][3])
                        : "r"(af[mt][0]), "r"(af[mt][1]), "r"(af[mt][2]), "r"(af[mt][3]),
                          "r"(bf[nt][0]), "r"(bf[nt][1]));
                }
        }
        __syncthreads();
    }

    // ---------------- fused epilogue: exact c + block top-4 per row ----------
    __shared__ float s_cv[128][2][4];
    __shared__ int   s_ci[128][2][4];
    float t0 = g_t[0];
    float t1s = g_t[1] * (1.0f / SCALE2);

#pragma unroll
    for (int mt = 0; mt < 2; mt++)
#pragma unroll
        for (int h = 0; h < 2; h++) {
            int rloc = wm * 32 + mt * 16 + h * 8 + (lane >> 2);
            int grow = rowBase + rloc;
            float di = g_dinv[grow];
            float v[4] = {-1e30f, -1e30f, -1e30f, -1e30f};
            int   id[4] = {0x7fffffff, 0x7fffffff, 0x7fffffff, 0x7fffffff};
#pragma unroll
            for (int nt = 0; nt < 8; nt++) {
                int gcol = colBase + wn * 64 + nt * 8 + (lane & 3) * 2;
                float2 a2 = *reinterpret_cast<const float2*>(A + (size_t)grow * GN + gcol);
                float s2a = (h == 0) ? acc[mt][nt][0] : acc[mt][nt][2];
                float s2b = (h == 0) ? acc[mt][nt][1] : acc[mt][nt][3];
                float p0 = t0 * (a2.x * di * g_dinv[gcol]) + t1s * s2a;
                float p1 = t0 * (a2.y * di * g_dinv[gcol + 1]) + t1s * s2b;
                if (grow == gcol)     p0 += 1.0f;
                if (grow == gcol + 1) p1 += 1.0f;
                topk_insert(p0 * g_dinv2[gcol],     gcol,     v, id);
                topk_insert(p1 * g_dinv2[gcol + 1], gcol + 1, v, id);
            }
            // merge across quad (lane&3)
#pragma unroll
            for (int d = 1; d <= 2; d <<= 1) {
                float ov[4]; int oi[4];
#pragma unroll
                for (int s = 0; s < 4; s++) {
                    ov[s] = __shfl_xor_sync(0xffffffffu, v[s], d);
                    oi[s] = __shfl_xor_sync(0xffffffffu, id[s], d);
                }
#pragma unroll
                for (int s = 0; s < 4; s++) topk_insert(ov[s], oi[s], v, id);
            }
            if ((lane & 3) == 0)
#pragma unroll
                for (int s = 0; s < 4; s++) {
                    s_cv[rloc][wn][s] = v[s];
                    s_ci[rloc][wn][s] = id[s];
                }
        }
    __syncthreads();

    if (tid < 128) {
        float v[4]; int id[4];
#pragma unroll
        for (int s = 0; s < 4; s++) { v[s] = s_cv[tid][0][s]; id[s] = s_ci[tid][0][s]; }
#pragma unroll
        for (int s = 0; s < 4; s++) topk_insert(s_cv[tid][1][s], s_ci[tid][1][s], v, id);
        size_t base = (size_t)(rowBase + tid) * 128 + blockIdx.x * 4;
#pragma unroll
        for (int s = 0; s < 4; s++) { g_cv[base + s] = v[s]; g_ci[base + s] = id[s]; }
    }
}

// ---------------- final merge (128 candidates/row) + output -----------------
__global__ void k_merge(const float* __restrict__ b, float* __restrict__ out) {
    int i = blockIdx.x;
    int tid = threadIdx.x;
    __shared__ float fv[4];
    __shared__ int   fi[4];

    if (tid < 32) {
        float v[4] = {-1e30f, -1e30f, -1e30f, -1e30f};
        int   id[4] = {0x7fffffff, 0x7fffffff, 0x7fffffff, 0x7fffffff};
        size_t base = (size_t)i * 128;
#pragma unroll
        for (int s = 0; s < 4; s++)
            topk_insert(g_cv[base + tid + s * 32], g_ci[base + tid + s * 32], v, id);
#pragma unroll
        for (int d = 1; d <= 16; d <<= 1) {
            float ov[4]; int oi[4];
#pragma unroll
            for (int s = 0; s < 4; s++) {
                ov[s] = __shfl_xor_sync(0xffffffffu, v[s], d);
                oi[s] = __shfl_xor_sync(0xffffffffu, id[s], d);
            }
#pragma unroll
            for (int s = 0; s < 4; s++) topk_insert(ov[s], oi[s], v, id);
        }
        if (tid == 0)
#pragma unroll
            for (int s = 0; s < 4; s++) { fv[s] = v[s]; fi[s] = id[s]; }
    }
    __syncthreads();

    if (tid < DOUT) {
        float di2 = g_dinv2[i];
        float s = b[tid];
#pragma unroll
        for (int q = 0; q < TOPK; q++)
            s += di2 * fv[q] * g_y[fi[q] * DOUT + tid];
        out[(size_t)i * DOUT + tid] = s;
    }
}

// ---------------- launch -----------------------------------------------------
extern "C" void kernel_launch(void* const* d_in, const int* in_sizes, int n_in,
                              void* d_out, int out_size) {
    const float* x     = (const float*)d_in[0];
    const float* A     = (const float*)d_in[1];
    const float* theta = (const float*)d_in[2];
    const float* W     = (const float*)d_in[3];
    const float* b     = (const float*)d_in[4];
    float* out = (float*)d_out;

    cudaFuncSetAttribute(k_gemm, cudaFuncAttributeMaxDynamicSharedMemorySize, DYN_SMEM);

    k_rowsumA<<<GN, 256>>>(A);
    k_sig<<<1, 32>>>(theta);
    k_build<<<dim3(128, 128), dim3(32, 8)>>>(A);
    k_rS<<<GN, 128>>>();
    k_rs2d2<<<GN, 128>>>();
    k_xw<<<GN, 64>>>(x, W);
    k_gemm<<<dim3(GN / 128, GN / 128), 256, DYN_SMEM>>>(A);
    k_merge<<<GN, 64>>>(b, out);
}

// round 17
// speedup vs baseline: 2.5521x; 1.0116x over previous
#include <cuda_runtime.h>
#include <cuda_fp16.h>
#include <cstdint>

#define GN 4096
#define DIN 64
#define DOUT 64
#define TOPK 4
#define SCALE 2048.0f
#define SCALE2 (2048.0f*2048.0f)

// ---------------- scratch (static device globals; no allocs allowed) --------
__device__ __half g_Sh [GN*(size_t)GN];   // S*SCALE, row-major  (32MB)
__device__ __half g_ShT[GN*(size_t)GN];   // S^T*SCALE           (32MB)
__device__ float  g_dinv[GN];
__device__ float  g_rS[GN];               // rowsum(S), exact fp32
__device__ float  g_dinv2[GN];
__device__ float  g_t[2];
__device__ float  g_y[GN*DOUT];
__device__ float  g_cv[GN*(size_t)128];   // per-(row, colblock) top-4 values (2MB)
__device__ int    g_ci[GN*(size_t)128];   // and indices                      (2MB)

// ---------------- small helpers --------------------------------------------
__device__ __forceinline__ float blk_reduce_sum(float s) {
    __shared__ float sm[8];
    for (int o = 16; o; o >>= 1) s += __shfl_down_sync(0xffffffffu, s, o);
    if ((threadIdx.x & 31) == 0) sm[threadIdx.x >> 5] = s;
    __syncthreads();
    float v = 0.f;
    if (threadIdx.x < 8) {
        v = sm[threadIdx.x];
        for (int o = 4; o; o >>= 1) v += __shfl_down_sync(0xffu, v, o);
    }
    return v;
}

__global__ void k_rowsumA(const float* __restrict__ A) {
    int row = blockIdx.x;
    const float4* Ar = reinterpret_cast<const float4*>(A + (size_t)row * GN);
    float s = 0.f;
    for (int j = threadIdx.x; j < GN / 4; j += blockDim.x) {
        float4 v = Ar[j];
        s += v.x + v.y + v.z + v.w;
    }
    float tot = blk_reduce_sum(s);
    if (threadIdx.x == 0) g_dinv[row] = rsqrtf(tot);
}

__global__ void k_sig(const float* __restrict__ theta) {
    if (threadIdx.x < 2) g_t[threadIdx.x] = 1.0f / (1.0f + expf(-theta[threadIdx.x]));
}

// rS[i] = dinv[i] * sum_j A[i,j]*dinv[j]   (exact fp32)
__global__ void k_rowsumS(const float* __restrict__ A) {
    int row = blockIdx.x;
    const float4* Ar = reinterpret_cast<const float4*>(A + (size_t)row * GN);
    const float4* Dv = reinterpret_cast<const float4*>(g_dinv);
    float s = 0.f;
    for (int j = threadIdx.x; j < GN / 4; j += blockDim.x) {
        float4 a = Ar[j];
        float4 d = Dv[j];
        s += a.x * d.x + a.y * d.y + a.z * d.z + a.w * d.w;
    }
    float tot = blk_reduce_sum(s);
    if (threadIdx.x == 0) g_rS[row] = g_dinv[row] * tot;
}

// rs2[i] = dinv[i] * sum_j A[i,j]*dinv[j]*rS[j]  (exact fp32); then dinv2
__global__ void k_rs2d2(const float* __restrict__ A) {
    int row = blockIdx.x;
    const float4* Ar = reinterpret_cast<const float4*>(A + (size_t)row * GN);
    const float4* Dv = reinterpret_cast<const float4*>(g_dinv);
    const float4* Rv = reinterpret_cast<const float4*>(g_rS);
    float s = 0.f;
    for (int j = threadIdx.x; j < GN / 4; j += blockDim.x) {
        float4 a = Ar[j];
        float4 d = Dv[j];
        float4 r = Rv[j];
        s += a.x * d.x * r.x + a.y * d.y * r.y + a.z * d.z * r.z + a.w * d.w * r.w;
    }
    float tot = blk_reduce_sum(s);
    if (threadIdx.x == 0) {
        float rs2 = g_dinv[row] * tot;
        float d2 = 1.0f + g_t[0] * g_rS[row] + g_t[1] * rs2;
        g_dinv2[row] = rsqrtf(d2);
    }
}

// build Sh + ShT (fp16, *SCALE)
__global__ void k_build(const float* __restrict__ A) {
    __shared__ float tile[32][33];
    int bx = blockIdx.x, by = blockIdx.y;
    int tx = threadIdx.x, ty = threadIdx.y;
    int col = bx * 32 + tx;
    float dc = g_dinv[col];
#pragma unroll
    for (int r = 0; r < 4; r++) {
        int row = by * 32 + ty + r * 8;
        float v = A[(size_t)row * GN + col] * g_dinv[row] * dc * SCALE;
        tile[ty + r * 8][tx] = v;
        g_Sh[(size_t)row * GN + col] = __float2half_rn(v);
    }
    __syncthreads();
#pragma unroll
    for (int r = 0; r < 4; r++) {
        int orow = bx * 32 + ty + r * 8;
        int ocol = by * 32 + tx;
        g_ShT[(size_t)orow * GN + ocol] = __float2half_rn(tile[tx][ty + r * 8]);
    }
}

// y = x @ W^T
__global__ void k_xw(const float* __restrict__ x, const float* __restrict__ W) {
    __shared__ float Wt[DIN * DOUT];
    __shared__ float xr[DIN];
    int row = blockIdx.x;
    for (int i = threadIdx.x; i < DOUT * DIN; i += 64) {
        int c = i / DIN, d = i % DIN;
        Wt[d * DOUT + c] = W[i];
    }
    if (threadIdx.x < DIN) xr[threadIdx.x] = x[row * DIN + threadIdx.x];
    __syncthreads();
    int c = threadIdx.x;
    float s = 0.f;
#pragma unroll
    for (int d = 0; d < DIN; d++) s += xr[d] * Wt[d * DOUT + c];
    g_y[row * DOUT + c] = s;
}

// ---------------- top-k primitive ------------------------------------------
__device__ __forceinline__ void topk_insert(float c, int j, float* v, int* id) {
    if (c > v[3] || (c == v[3] && j < id[3])) {
        v[3] = c; id[3] = j;
#pragma unroll
        for (int s = 3; s > 0; s--) {
            if (v[s] > v[s - 1] || (v[s] == v[s - 1] && id[s] < id[s - 1])) {
                float tv = v[s]; v[s] = v[s - 1]; v[s - 1] = tv;
                int ti = id[s]; id[s] = id[s - 1]; id[s - 1] = ti;
            }
        }
    }
}

// ---------------- HMMA GEMM + fused top-4 candidate epilogue ---------------
#define ST 3
#define KC 64
#define NC (GN / KC)
#define A_BYTES (128 * 128)
#define B_BYTES (128 * 128)
#define STAGE_BYTES (A_BYTES + B_BYTES)
#define DYN_SMEM (ST * STAGE_BYTES)  // 96KB

__device__ __forceinline__ uint32_t sw128(uint32_t off) {
    return off ^ ((off >> 3) & 0x70);
}

__global__ void __launch_bounds__(256, 2) k_gemm(const float* __restrict__ A) {
    extern __shared__ char dsm[];
    uint32_t sbase;
    asm("{ .reg .u64 t; cvta.to.shared.u64 t, %1; cvt.u32.u64 %0, t; }"
        : "=r"(sbase) : "l"(dsm));

    const __half* Ag = g_Sh;
    const __half* Bg = g_ShT;
    int tid = threadIdx.x, warp = tid >> 5, lane = tid & 31;
    int wm = warp & 3;
    int wn = warp >> 2;
    int rowBase = blockIdx.y * 128;
    int colBase = blockIdx.x * 128;

    float acc[2][8][4];
#pragma unroll
    for (int a = 0; a < 2; a++)
#pragma unroll
        for (int b = 0; b < 8; b++)
#pragma unroll
            for (int c = 0; c < 4; c++) acc[a][b][c] = 0.f;

    auto load_chunk = [&](int j) {
        uint32_t st0 = sbase + (j % ST) * STAGE_BYTES;
        int k0 = j * KC;
#pragma unroll
        for (int t = 0; t < 8; t++) {
            int q = tid + t * 256;
            const __half* src;
            uint32_t dst;
            if (q < 1024) {
                int r = q >> 3, c16 = q & 7;
                src = Ag + (size_t)(rowBase + r) * GN + k0 + c16 * 8;
                dst = st0 + sw128(r * 128 + c16 * 16);
            } else {
                int idx = q - 1024;
                int r = idx >> 3, c16 = idx & 7;
                src = Bg + (size_t)(colBase + r) * GN + k0 + c16 * 8;
                dst = st0 + A_BYTES + sw128(r * 128 + c16 * 16);
            }
            asm volatile("cp.async.cg.shared.global [%0],[%1],16;\n" :: "r"(dst), "l"(src));
        }
        asm volatile("cp.async.commit_group;\n");
    };

    load_chunk(0);
    load_chunk(1);

    for (int i = 0; i < NC; i++) {
        // wait for chunk i (1 group may remain in flight), then one sync that
        // both publishes stage i and retires consumers of stage (i-1)%ST
        asm volatile("cp.async.wait_group 1;\n");
        __syncthreads();
        if (i + 2 < NC) load_chunk(i + 2);
        else asm volatile("cp.async.commit_group;\n");

        uint32_t aB = sbase + (i % ST) * STAGE_BYTES;
        uint32_t bB = aB + A_BYTES;
#pragma unroll
        for (int ks = 0; ks < 4; ks++) {
            int kk = ks * 16;
            uint32_t af[2][4];
#pragma unroll
            for (int mt = 0; mt < 2; mt++) {
                int m = wm * 32 + mt * 16 + (lane & 15);
                uint32_t off = m * 128 + kk * 2 + (lane >> 4) * 16;
                uint32_t addr = aB + sw128(off);
                asm volatile("ldmatrix.sync.aligned.m8n8.x4.shared.b16 {%0,%1,%2,%3},[%4];"
                             : "=r"(af[mt][0]), "=r"(af[mt][1]), "=r"(af[mt][2]), "=r"(af[mt][3])
                             : "r"(addr));
            }
            uint32_t bf[8][2];
#pragma unroll
            for (int nb = 0; nb < 4; nb++) {
                int sel = lane >> 3;
                int nn = wn * 64 + nb * 16 + (sel >> 1) * 8 + (lane & 7);
                uint32_t off = nn * 128 + kk * 2 + (sel & 1) * 16;
                uint32_t addr = bB + sw128(off);
                uint32_t r0, r1, r2, r3;
                asm volatile("ldmatrix.sync.aligned.m8n8.x4.shared.b16 {%0,%1,%2,%3},[%4];"
                             : "=r"(r0), "=r"(r1), "=r"(r2), "=r"(r3) : "r"(addr));
                bf[nb * 2][0] = r0; bf[nb * 2][1] = r1;
                bf[nb * 2 + 1][0] = r2; bf[nb * 2 + 1][1] = r3;
            }
#pragma unroll
            for (int mt = 0; mt < 2; mt++)
#pragma unroll
                for (int nt = 0; nt < 8; nt++) {
                    asm volatile(
                        "mma.sync.aligned.m16n8k16.row.col.f32.f16.f16.f32 "
                        "{%0,%1,%2,%3},{%4,%5,%6,%7},{%8,%9},{%0,%1,%2,%3};"
                        : "+f"(acc[mt][nt][0]), "+f"(acc[mt][nt][1]),
                          "+f"(acc[mt][nt][2]), "+f"(acc[mt][nt][3])
                        : "r"(af[mt][0]), "r"(af[mt][1]), "r"(af[mt][2]), "r"(af[mt][3]),
                          "r"(bf[nt][0]), "r"(bf[nt][1]));
                }
        }
    }
    __syncthreads();

    // ---------------- fused epilogue: exact c + block top-4 per row ----------
    __shared__ float s_cv[128][2][4];
    __shared__ int   s_ci[128][2][4];
    float t0 = g_t[0];
    float t1s = g_t[1] * (1.0f / SCALE2);

#pragma unroll
    for (int mt = 0; mt < 2; mt++)
#pragma unroll
        for (int h = 0; h < 2; h++) {
            int rloc = wm * 32 + mt * 16 + h * 8 + (lane >> 2);
            int grow = rowBase + rloc;
            float di = g_dinv[grow];
            float v[4] = {-1e30f, -1e30f, -1e30f, -1e30f};
            int   id[4] = {0x7fffffff, 0x7fffffff, 0x7fffffff, 0x7fffffff};
#pragma unroll
            for (int nt = 0; nt < 8; nt++) {
                int gcol = colBase + wn * 64 + nt * 8 + (lane & 3) * 2;
                float2 a2 = *reinterpret_cast<const float2*>(A + (size_t)grow * GN + gcol);
                float s2a = (h == 0) ? acc[mt][nt][0] : acc[mt][nt][2];
                float s2b = (h == 0) ? acc[mt][nt][1] : acc[mt][nt][3];
                float p0 = t0 * (a2.x * di * g_dinv[gcol]) + t1s * s2a;
                float p1 = t0 * (a2.y * di * g_dinv[gcol + 1]) + t1s * s2b;
                if (grow == gcol)     p0 += 1.0f;
                if (grow == gcol + 1) p1 += 1.0f;
                topk_insert(p0 * g_dinv2[gcol],     gcol,     v, id);
                topk_insert(p1 * g_dinv2[gcol + 1], gcol + 1, v, id);
            }
#pragma unroll
            for (int d = 1; d <= 2; d <<= 1) {
                float ov[4]; int oi[4];
#pragma unroll
                for (int s = 0; s < 4; s++) {
                    ov[s] = __shfl_xor_sync(0xffffffffu, v[s], d);
                    oi[s] = __shfl_xor_sync(0xffffffffu, id[s], d);
                }
#pragma unroll
                for (int s = 0; s < 4; s++) topk_insert(ov[s], oi[s], v, id);
            }
            if ((lane & 3) == 0)
#pragma unroll
                for (int s = 0; s < 4; s++) {
                    s_cv[rloc][wn][s] = v[s];
                    s_ci[rloc][wn][s] = id[s];
                }
        }
    __syncthreads();

    if (tid < 128) {
        float v[4]; int id[4];
#pragma unroll
        for (int s = 0; s < 4; s++) { v[s] = s_cv[tid][0][s]; id[s] = s_ci[tid][0][s]; }
#pragma unroll
        for (int s = 0; s < 4; s++) topk_insert(s_cv[tid][1][s], s_ci[tid][1][s], v, id);
        size_t base = (size_t)(rowBase + tid) * 128 + blockIdx.x * 4;
#pragma unroll
        for (int s = 0; s < 4; s++) { g_cv[base + s] = v[s]; g_ci[base + s] = id[s]; }
    }
}

// ---------------- final merge (128 candidates/row) + output -----------------
__global__ void k_merge(const float* __restrict__ b, float* __restrict__ out) {
    int i = blockIdx.x;
    int tid = threadIdx.x;
    __shared__ float fv[4];
    __shared__ int   fi[4];

    if (tid < 32) {
        float v[4] = {-1e30f, -1e30f, -1e30f, -1e30f};
        int   id[4] = {0x7fffffff, 0x7fffffff, 0x7fffffff, 0x7fffffff};
        size_t base = (size_t)i * 128;
#pragma unroll
        for (int s = 0; s < 4; s++)
            topk_insert(g_cv[base + tid + s * 32], g_ci[base + tid + s * 32], v, id);
#pragma unroll
        for (int d = 1; d <= 16; d <<= 1) {
            float ov[4]; int oi[4];
#pragma unroll
            for (int s = 0; s < 4; s++) {
                ov[s] = __shfl_xor_sync(0xffffffffu, v[s], d);
                oi[s] = __shfl_xor_sync(0xffffffffu, id[s], d);
            }
#pragma unroll
            for (int s = 0; s < 4; s++) topk_insert(ov[s], oi[s], v, id);
        }
        if (tid == 0)
#pragma unroll
            for (int s = 0; s < 4; s++) { fv[s] = v[s]; fi[s] = id[s]; }
    }
    __syncthreads();

    if (tid < DOUT) {
        float di2 = g_dinv2[i];
        float s = b[tid];
#pragma unroll
        for (int q = 0; q < TOPK; q++)
            s += di2 * fv[q] * g_y[fi[q] * DOUT + tid];
        out[(size_t)i * DOUT + tid] = s;
    }
}

// ---------------- launch -----------------------------------------------------
extern "C" void kernel_launch(void* const* d_in, const int* in_sizes, int n_in,
                              void* d_out, int out_size) {
    const float* x     = (const float*)d_in[0];
    const float* A     = (const float*)d_in[1];
    const float* theta = (const float*)d_in[2];
    const float* W     = (const float*)d_in[3];
    const float* b     = (const float*)d_in[4];
    float* out = (float*)d_out;

    cudaFuncSetAttribute(k_gemm, cudaFuncAttributeMaxDynamicSharedMemorySize, DYN_SMEM);

    k_rowsumA<<<GN, 256>>>(A);
    k_sig<<<1, 32>>>(theta);
    k_rowsumS<<<GN, 256>>>(A);
    k_rs2d2<<<GN, 256>>>(A);
    k_build<<<dim3(128, 128), dim3(32, 8)>>>(A);
    k_xw<<<GN, 64>>>(x, W);
    k_gemm<<<dim3(GN / 128, GN / 128), 256, DYN_SMEM>>>(A);
    k_merge<<<GN, 64>>>(b, out);
}